// round 16
// baseline (speedup 1.0000x reference)
#include <cuda_runtime.h>
#include <cuda_fp16.h>
#include <cstdint>

// Problem constants
#define BATCH 8
#define NPIX  4096          // 64*64
#define CIN   256
#define DHEAD 32
#define MROWS (BATCH*NPIX)  // 32768

#define QT 64               // q rows per attn CTA (4 warps x 16 rows)
#define MT 64               // k/v rows per inner tile
#define NSPLIT 4            // kv splits
#define KVH (NPIX/NSPLIT)   // kv rows per split = 1024
#define NTILES (KVH/MT)     // 16 tiles per split

// smem strides (in halves). 40 halves = 80B rows: 16B aligned.
#define TS 40
#define WQS 104
#define WOS 136

#define LOG2E 1.4426950408889634f

// fp16 scratch (device globals; no runtime allocation allowed)
__device__ __half g_q[MROWS * DHEAD];
__device__ __half g_k[MROWS * DHEAD];
__device__ __half g_v[MROWS * DHEAD];
// split-KV partials: unnormalized O (fp32) and (m, l) per row, per split
__device__ float  g_po[NSPLIT * MROWS * DHEAD];   // 16 MB
__device__ float2 g_ml[NSPLIT * MROWS];           // 1 MB

// ---------------------------------------------------------------------------
// helpers
// ---------------------------------------------------------------------------
__device__ __forceinline__ uint32_t pack2(float lo, float hi) {
    __half2 h = __floats2half2_rn(lo, hi);
    return *reinterpret_cast<uint32_t*>(&h);
}
__device__ __forceinline__ uint32_t h2exp2(uint32_t u) {
    uint32_t r;
    asm("ex2.approx.f16x2 %0, %1;" : "=r"(r) : "r"(u));
    return r;
}

__device__ __forceinline__ void mma_f16(float* d, const uint32_t* a,
                                        uint32_t b0, uint32_t b1, const float* c)
{
    asm("mma.sync.aligned.m16n8k16.row.col.f32.f16.f16.f32 "
        "{%0,%1,%2,%3}, {%4,%5,%6,%7}, {%8,%9}, {%10,%11,%12,%13};"
        : "=f"(d[0]), "=f"(d[1]), "=f"(d[2]), "=f"(d[3])
        : "r"(a[0]), "r"(a[1]), "r"(a[2]), "r"(a[3]),
          "r"(b0), "r"(b1),
          "f"(c[0]), "f"(c[1]), "f"(c[2]), "f"(c[3]));
}

__device__ __forceinline__ void ldsm4(uint32_t* r, uint32_t addr) {
    asm volatile("ldmatrix.sync.aligned.m8n8.x4.shared.b16 {%0,%1,%2,%3}, [%4];"
                 : "=r"(r[0]), "=r"(r[1]), "=r"(r[2]), "=r"(r[3]) : "r"(addr));
}
__device__ __forceinline__ void ldsm4t(uint32_t* r, uint32_t addr) {
    asm volatile("ldmatrix.sync.aligned.m8n8.x4.trans.shared.b16 {%0,%1,%2,%3}, [%4];"
                 : "=r"(r[0]), "=r"(r[1]), "=r"(r[2]), "=r"(r[3]) : "r"(addr));
}

__device__ __forceinline__ void cp16(uint32_t smem_addr, const void* gptr) {
    asm volatile("cp.async.cg.shared.global [%0], [%1], 16;"
                 :: "r"(smem_addr), "l"(gptr) : "memory");
}
__device__ __forceinline__ void cp_commit() {
    asm volatile("cp.async.commit_group;" ::: "memory");
}
__device__ __forceinline__ void cp_wait0() {
    asm volatile("cp.async.wait_group 0;" ::: "memory");
}

// ---------------------------------------------------------------------------
// Kernel 1: QKV projection (round-7 config, unchanged).
// ---------------------------------------------------------------------------
__global__ void __launch_bounds__(256) qkv_kernel(
    const float* __restrict__ x,
    const float* __restrict__ Wq, const float* __restrict__ bq,
    const float* __restrict__ Wk, const float* __restrict__ bk,
    const float* __restrict__ Wv, const float* __restrict__ bv)
{
    __shared__ __half Xs[2][128 * TS];
    __shared__ __half Ws[2][32 * WQS];
    __shared__ float bsm[96];

    const int tid = threadIdx.x;
    const int warp = tid >> 5, lane = tid & 31;
    const int gid = lane >> 2, tig = lane & 3;
    const int row0 = blockIdx.x * 128;

    const uint32_t xs_base = (uint32_t)__cvta_generic_to_shared(&Xs[0][0]);
    const uint32_t ws_base = (uint32_t)__cvta_generic_to_shared(&Ws[0][0]);
    const uint32_t XBUF = 128 * TS * 2;
    const uint32_t WBUF = 32 * WQS * 2;

    if (tid < 96) bsm[tid] = (tid < 32) ? bq[tid] : (tid < 64 ? bk[tid - 32] : bv[tid - 64]);

    const float* wmat[3] = {Wq, Wk, Wv};

    float acc[12][4];
#pragma unroll
    for (int nb = 0; nb < 12; nb++)
#pragma unroll
        for (int r = 0; r < 4; r++) acc[nb][r] = 0.f;

    float4 xr[4], wr[3];
#pragma unroll
    for (int it = 0; it < 4; it++) {
        int i = tid + it * 256;
        int r = i >> 3, c4 = i & 7;
        xr[it] = *(const float4*)(x + (size_t)(row0 + r) * CIN + c4 * 4);
    }
#pragma unroll
    for (int m = 0; m < 3; m++) {
        int kk = tid >> 3, c4 = tid & 7;
        wr[m] = *(const float4*)(wmat[m] + (size_t)kk * DHEAD + c4 * 4);
    }
#pragma unroll
    for (int it = 0; it < 4; it++) {
        int i = tid + it * 256;
        int r = i >> 3, c4 = i & 7;
        uint2 p; p.x = pack2(xr[it].x, xr[it].y); p.y = pack2(xr[it].z, xr[it].w);
        *(uint2*)&Xs[0][r * TS + c4 * 4] = p;
    }
#pragma unroll
    for (int m = 0; m < 3; m++) {
        int kk = tid >> 3, c4 = tid & 7;
        uint2 p; p.x = pack2(wr[m].x, wr[m].y); p.y = pack2(wr[m].z, wr[m].w);
        *(uint2*)&Ws[0][kk * WQS + m * 32 + c4 * 4] = p;
    }
    __syncthreads();

    for (int c = 0; c < 8; c++) {
        const int cur = c & 1;

        if (c + 1 < 8) {
            int kc = (c + 1) * 32;
#pragma unroll
            for (int it = 0; it < 4; it++) {
                int i = tid + it * 256;
                int r = i >> 3, c4 = i & 7;
                xr[it] = *(const float4*)(x + (size_t)(row0 + r) * CIN + kc + c4 * 4);
            }
#pragma unroll
            for (int m = 0; m < 3; m++) {
                int kk = tid >> 3, c4 = tid & 7;
                wr[m] = *(const float4*)(wmat[m] + (size_t)(kc + kk) * DHEAD + c4 * 4);
            }
        }

        uint32_t a[2][4];
#pragma unroll
        for (int ks = 0; ks < 2; ks++) {
            uint32_t addr = xs_base + cur * XBUF +
                ((warp * 16 + ((lane >> 3) & 1) * 8 + (lane & 7)) * TS) * 2 +
                (ks * 16 + (lane >> 4) * 8) * 2;
            ldsm4(a[ks], addr);
        }
#pragma unroll
        for (int ks = 0; ks < 2; ks++) {
#pragma unroll
            for (int nbp = 0; nbp < 6; nbp++) {
                uint32_t wb[4];
                uint32_t addr = ws_base + cur * WBUF +
                    ((ks * 16 + ((lane >> 3) & 1) * 8 + (lane & 7)) * WQS) * 2 +
                    (nbp * 16 + (lane >> 4) * 8) * 2;
                ldsm4t(wb, addr);
                mma_f16(acc[2 * nbp],     a[ks], wb[0], wb[1], acc[2 * nbp]);
                mma_f16(acc[2 * nbp + 1], a[ks], wb[2], wb[3], acc[2 * nbp + 1]);
            }
        }

        if (c + 1 < 8) {
#pragma unroll
            for (int it = 0; it < 4; it++) {
                int i = tid + it * 256;
                int r = i >> 3, c4 = i & 7;
                uint2 p; p.x = pack2(xr[it].x, xr[it].y); p.y = pack2(xr[it].z, xr[it].w);
                *(uint2*)&Xs[cur ^ 1][r * TS + c4 * 4] = p;
            }
#pragma unroll
            for (int m = 0; m < 3; m++) {
                int kk = tid >> 3, c4 = tid & 7;
                uint2 p; p.x = pack2(wr[m].x, wr[m].y); p.y = pack2(wr[m].z, wr[m].w);
                *(uint2*)&Ws[cur ^ 1][kk * WQS + m * 32 + c4 * 4] = p;
            }
        }
        __syncthreads();
    }

#pragma unroll
    for (int nb = 0; nb < 12; nb++) {
        int cc = nb * 8 + 2 * tig;
        float b0 = bsm[cc], b1 = bsm[cc + 1];
        int r0 = row0 + warp * 16 + gid;
        __half* dst; int col;
        if (nb < 4)      { dst = g_q; col = cc; }
        else if (nb < 8) { dst = g_k; col = cc - 32; }
        else             { dst = g_v; col = cc - 64; }
        *(uint32_t*)(dst + (size_t)r0 * DHEAD + col) =
            pack2(fmaxf(acc[nb][0] + b0, 0.f), fmaxf(acc[nb][1] + b1, 0.f));
        *(uint32_t*)(dst + (size_t)(r0 + 8) * DHEAD + col) =
            pack2(fmaxf(acc[nb][2] + b0, 0.f), fmaxf(acc[nb][3] + b1, 0.f));
    }
}

// ---------------------------------------------------------------------------
// Kernel 2: split-KV flash attention partial (NSPLIT=4).
// Grid (64, 8, 4) = 2048 CTAs, block 128 (4 warps), 5 CTAs/SM target.
// Mainloop per warp identical to rounds 13-15. cp.async K/V staging.
// ---------------------------------------------------------------------------
__global__ void __launch_bounds__(128, 5) attn_partial_kernel()
{
    __shared__ __half Ks[2][MT * TS];      // 2 x 5 KB
    __shared__ __half Vs[2][MT * TS];      // 2 x 5 KB

    const int b   = blockIdx.y;
    const int qt  = blockIdx.x;
    const int z   = blockIdx.z;            // kv split
    const int tid = threadIdx.x;
    const int warp = tid >> 5, lane = tid & 31;
    const int gid = lane >> 2, tig = lane & 3;

    const uint32_t ks_base = (uint32_t)__cvta_generic_to_shared(&Ks[0][0]);
    const uint32_t vs_base = (uint32_t)__cvta_generic_to_shared(&Vs[0][0]);
    const uint32_t BUF = MT * TS * 2;

    const uint32_t ones = (gid == 0) ? 0x3C003C00u : 0u;

    const __half* qg = g_q + ((size_t)b * NPIX + (size_t)qt * QT + warp * 16) * DHEAD;
    const __half* kg = g_k + (size_t)b * NPIX * DHEAD + (size_t)z * KVH * DHEAD;
    const __half* vg = g_v + (size_t)b * NPIX * DHEAD + (size_t)z * KVH * DHEAD;

    uint32_t qa[2][4];
#pragma unroll
    for (int ks = 0; ks < 2; ks++) {
        qa[ks][0] = *(const uint32_t*)(qg + (size_t)(gid)     * DHEAD + ks * 16 + 2 * tig);
        qa[ks][1] = *(const uint32_t*)(qg + (size_t)(gid + 8) * DHEAD + ks * 16 + 2 * tig);
        qa[ks][2] = *(const uint32_t*)(qg + (size_t)(gid)     * DHEAD + ks * 16 + 8 + 2 * tig);
        qa[ks][3] = *(const uint32_t*)(qg + (size_t)(gid + 8) * DHEAD + ks * 16 + 8 + 2 * tig);
    }

    float O[5][4];
#pragma unroll
    for (int nb = 0; nb < 5; nb++)
#pragma unroll
        for (int r = 0; r < 4; r++) O[nb][r] = 0.f;
    float mi0 = -1e30f, mi1 = -1e30f;

    const int s0 = tid, s1 = tid + 128;
    const int r0s = s0 >> 2, c0s = (s0 & 3) * 8;
    const int r1s = s1 >> 2, c1s = (s1 & 3) * 8;

    cp16(ks_base + (r0s * TS + c0s) * 2, kg + (size_t)r0s * DHEAD + c0s);
    cp16(ks_base + (r1s * TS + c1s) * 2, kg + (size_t)r1s * DHEAD + c1s);
    cp16(vs_base + (r0s * TS + c0s) * 2, vg + (size_t)r0s * DHEAD + c0s);
    cp16(vs_base + (r1s * TS + c1s) * 2, vg + (size_t)r1s * DHEAD + c1s);
    cp_commit();
    cp_wait0();
    __syncthreads();

    for (int mt = 0; mt < NTILES; mt++) {
        const int cur = mt & 1;

        if (mt + 1 < NTILES) {
            const __half* kt = kg + (size_t)(mt + 1) * MT * DHEAD;
            const __half* vt = vg + (size_t)(mt + 1) * MT * DHEAD;
            const uint32_t kb2 = ks_base + (cur ^ 1) * BUF;
            const uint32_t vb2 = vs_base + (cur ^ 1) * BUF;
            cp16(kb2 + (r0s * TS + c0s) * 2, kt + (size_t)r0s * DHEAD + c0s);
            cp16(kb2 + (r1s * TS + c1s) * 2, kt + (size_t)r1s * DHEAD + c1s);
            cp16(vb2 + (r0s * TS + c0s) * 2, vt + (size_t)r0s * DHEAD + c0s);
            cp16(vb2 + (r1s * TS + c1s) * 2, vt + (size_t)r1s * DHEAD + c1s);
            cp_commit();
        }

        // ---- mma1: S(16x64) = Q K^T ----
        float S[8][4];
#pragma unroll
        for (int nb = 0; nb < 8; nb++) {
#pragma unroll
            for (int r = 0; r < 4; r++) S[nb][r] = 0.f;
            uint32_t kb[4];
            uint32_t addr = ks_base + cur * BUF +
                ((nb * 8 + (lane & 7)) * TS) * 2 + (lane >> 3) * 16;
            ldsm4(kb, addr);
            mma_f16(S[nb], qa[0], kb[0], kb[1], S[nb]);
            mma_f16(S[nb], qa[1], kb[2], kb[3], S[nb]);
        }

        // ---- online softmax (rows gid, gid+8) ----
        float rm0 = -1e30f, rm1 = -1e30f;
#pragma unroll
        for (int nb = 0; nb < 8; nb++) {
            rm0 = fmaxf(rm0, fmaxf(S[nb][0], S[nb][1]));
            rm1 = fmaxf(rm1, fmaxf(S[nb][2], S[nb][3]));
        }
        rm0 = fmaxf(rm0, __shfl_xor_sync(0xffffffffu, rm0, 1));
        rm0 = fmaxf(rm0, __shfl_xor_sync(0xffffffffu, rm0, 2));
        rm1 = fmaxf(rm1, __shfl_xor_sync(0xffffffffu, rm1, 1));
        rm1 = fmaxf(rm1, __shfl_xor_sync(0xffffffffu, rm1, 2));

        float nm0 = fmaxf(mi0, rm0), nm1 = fmaxf(mi1, rm1);
        float corr0 = exp2f((mi0 - nm0) * LOG2E);
        float corr1 = exp2f((mi1 - nm1) * LOG2E);
        mi0 = nm0; mi1 = nm1;
        const float nc0 = nm0 * (-LOG2E), nc1 = nm1 * (-LOG2E);

        uint32_t P[4][4];
#pragma unroll
        for (int nb = 0; nb < 8; nb++) {
            float u0 = fmaf(S[nb][0], LOG2E, nc0);
            float u1 = fmaf(S[nb][1], LOG2E, nc0);
            float u2 = fmaf(S[nb][2], LOG2E, nc1);
            float u3 = fmaf(S[nb][3], LOG2E, nc1);
            int ks2 = nb >> 1, hi = (nb & 1) * 2;
            P[ks2][hi]     = h2exp2(pack2(u0, u1));
            P[ks2][hi + 1] = h2exp2(pack2(u2, u3));
        }

#pragma unroll
        for (int nb = 0; nb < 5; nb++) {
            O[nb][0] *= corr0; O[nb][1] *= corr0;
            O[nb][2] *= corr1; O[nb][3] *= corr1;
        }

        // ---- mma2: O += P V ;  l += P @ ones ----
#pragma unroll
        for (int ks2 = 0; ks2 < 4; ks2++) {
            const uint32_t* a = P[ks2];
#pragma unroll
            for (int dbp = 0; dbp < 2; dbp++) {
                uint32_t vb[4];
                uint32_t addr = vs_base + cur * BUF +
                    ((ks2 * 16 + ((lane >> 3) & 1) * 8 + (lane & 7)) * TS) * 2 +
                    dbp * 32 + (lane >> 4) * 16;
                ldsm4t(vb, addr);
                mma_f16(O[2 * dbp],     a, vb[0], vb[1], O[2 * dbp]);
                mma_f16(O[2 * dbp + 1], a, vb[2], vb[3], O[2 * dbp + 1]);
            }
            mma_f16(O[4], a, ones, ones, O[4]);
        }

        if (mt + 1 < NTILES) cp_wait0();
        __syncthreads();
    }

    // ---- write partials (unnormalized) ----
    const size_t row = (size_t)b * NPIX + (size_t)qt * QT + warp * 16 + gid;
    float* po = g_po + (size_t)z * MROWS * DHEAD;
#pragma unroll
    for (int db = 0; db < 4; db++) {
        int cc = db * 8 + 2 * tig;
        *(float2*)(po + row * DHEAD + cc)       = make_float2(O[db][0], O[db][1]);
        *(float2*)(po + (row + 8) * DHEAD + cc) = make_float2(O[db][2], O[db][3]);
    }
    if (tig == 0) {
        g_ml[(size_t)z * MROWS + row]     = make_float2(mi0, O[4][0]);
        g_ml[(size_t)z * MROWS + row + 8] = make_float2(mi1, O[4][2]);
    }
}

// ---------------------------------------------------------------------------
// Kernel 3: combine NSPLIT partials + output projection.
// Grid (256, 2), block 256.
// ---------------------------------------------------------------------------
__global__ void __launch_bounds__(256) combine_proj_kernel(
    const float* __restrict__ Wo,
    const float* __restrict__ bo,
    float* __restrict__ out)
{
    __shared__ __half Wos[32 * WOS];
    __shared__ float bos[128];

    const int tid = threadIdx.x;
    const int warp = tid >> 5, lane = tid & 31;
    const int gid = lane >> 2, tig = lane & 3;
    const int row0 = blockIdx.x * 128;
    const int n0   = blockIdx.y * 128;

    const uint32_t wo_base = (uint32_t)__cvta_generic_to_shared(&Wos[0]);

    if (tid < 128) bos[tid] = bo[n0 + tid];
#pragma unroll
    for (int it = 0; it < 4; it++) {
        int i = tid + it * 256;
        int kk = i >> 5, c4 = i & 31;
        float4 v = *(const float4*)(Wo + (size_t)kk * CIN + n0 + c4 * 4);
        uint2 p; p.x = pack2(v.x, v.y); p.y = pack2(v.z, v.w);
        *(uint2*)&Wos[kk * WOS + c4 * 4] = p;
    }

    // ---- per-thread combine over NSPLIT partials -> A-fragments ----
    const size_t r0 = row0 + warp * 16 + gid;
    const size_t r1 = r0 + 8;

    float m0 = -1e30f, m1 = -1e30f;
    float2 ml0[NSPLIT], ml1[NSPLIT];
#pragma unroll
    for (int z = 0; z < NSPLIT; z++) {
        ml0[z] = g_ml[(size_t)z * MROWS + r0];
        ml1[z] = g_ml[(size_t)z * MROWS + r1];
        m0 = fmaxf(m0, ml0[z].x);
        m1 = fmaxf(m1, ml1[z].x);
    }
    float w0[NSPLIT], w1[NSPLIT];
    float lsum0 = 0.f, lsum1 = 0.f;
#pragma unroll
    for (int z = 0; z < NSPLIT; z++) {
        w0[z] = exp2f((ml0[z].x - m0) * LOG2E);
        w1[z] = exp2f((ml1[z].x - m1) * LOG2E);
        lsum0 += ml0[z].y * w0[z];
        lsum1 += ml1[z].y * w1[z];
    }
    float inv0 = 1.f / lsum0, inv1 = 1.f / lsum1;
#pragma unroll
    for (int z = 0; z < NSPLIT; z++) { w0[z] *= inv0; w1[z] *= inv1; }

    uint32_t aep[2][4];
#pragma unroll
    for (int ks = 0; ks < 2; ks++) {
#pragma unroll
        for (int half8 = 0; half8 < 2; half8++) {
            int cc = ks * 16 + half8 * 8 + 2 * tig;
            float s0x = 0.f, s0y = 0.f, s1x = 0.f, s1y = 0.f;
#pragma unroll
            for (int z = 0; z < NSPLIT; z++) {
                const float* po = g_po + (size_t)z * MROWS * DHEAD;
                float2 a0 = *(const float2*)(po + r0 * DHEAD + cc);
                float2 a1 = *(const float2*)(po + r1 * DHEAD + cc);
                s0x += a0.x * w0[z]; s0y += a0.y * w0[z];
                s1x += a1.x * w1[z]; s1y += a1.y * w1[z];
            }
            aep[ks][half8 * 2]     = pack2(s0x, s0y);
            aep[ks][half8 * 2 + 1] = pack2(s1x, s1y);
        }
    }
    __syncthreads();

    float acc[16][4];
#pragma unroll
    for (int nb = 0; nb < 16; nb++)
#pragma unroll
        for (int r = 0; r < 4; r++) acc[nb][r] = 0.f;

#pragma unroll
    for (int ks = 0; ks < 2; ks++) {
#pragma unroll
        for (int nbp = 0; nbp < 8; nbp++) {
            uint32_t wb[4];
            uint32_t addr = wo_base +
                ((ks * 16 + ((lane >> 3) & 1) * 8 + (lane & 7)) * WOS) * 2 +
                (nbp * 16 + (lane >> 4) * 8) * 2;
            ldsm4t(wb, addr);
            mma_f16(acc[2 * nbp],     aep[ks], wb[0], wb[1], acc[2 * nbp]);
            mma_f16(acc[2 * nbp + 1], aep[ks], wb[2], wb[3], acc[2 * nbp + 1]);
        }
    }

#pragma unroll
    for (int nb = 0; nb < 16; nb++) {
        int cc = nb * 8 + 2 * tig;
        float b0 = bos[cc], b1 = bos[cc + 1];
        float2 lo, hi;
        lo.x = fmaxf(acc[nb][0] + b0, 0.f); lo.y = fmaxf(acc[nb][1] + b1, 0.f);
        hi.x = fmaxf(acc[nb][2] + b0, 0.f); hi.y = fmaxf(acc[nb][3] + b1, 0.f);
        *(float2*)(out + r0 * CIN + n0 + cc) = lo;
        *(float2*)(out + r1 * CIN + n0 + cc) = hi;
    }
}

// ---------------------------------------------------------------------------
extern "C" void kernel_launch(void* const* d_in, const int* in_sizes, int n_in,
                              void* d_out, int out_size)
{
    const float* x  = (const float*)d_in[0];
    const float* Wq = (const float*)d_in[1];
    const float* bq = (const float*)d_in[2];
    const float* Wk = (const float*)d_in[3];
    const float* bk = (const float*)d_in[4];
    const float* Wv = (const float*)d_in[5];
    const float* bv = (const float*)d_in[6];
    const float* Wo = (const float*)d_in[7];
    const float* bo = (const float*)d_in[8];
    float* out = (float*)d_out;

    qkv_kernel<<<MROWS / 128, 256>>>(x, Wq, bq, Wk, bk, Wv, bv);
    attn_partial_kernel<<<dim3(NPIX / QT, BATCH, NSPLIT), 128>>>();
    combine_proj_kernel<<<dim3(MROWS / 128, 2), 256>>>(Wo, bo, out);
}